// round 14
// baseline (speedup 1.0000x reference)
#include <cuda_runtime.h>
#include <cuda_fp16.h>
#include <math.h>
#include <cstdint>

// Problem constants
#define NB 4
#define LSEQ 2048
#define DM 1024
#define NHEAD 16
#define HD 64
#define MROWS (NB * LSEQ)   // 8192
#define CH 64
#define NC (LSEQ / CH)      // 32
#define NH (NB * NHEAD)     // 64

// Scratch (device globals; no allocation allowed)
__device__ __half g_qh[MROWS * DM];         // elu(q)+1 fp16
__device__ __half g_kh[MROWS * DM];         // elu(k)+1 fp16
__device__ __half g_vh[MROWS * DM];         // v projection fp16
__device__ float g_S [NH * NC * HD * HD];
__device__ float g_qs[NH * NC * HD];

// fp16 GEMM operand scratch
__device__ __half g_Ah[3 * MROWS * DM];     // q,k,v inputs (att reuses slot 0)
__device__ __half g_W [4 * DM * DM];        // transposed [n][k]; slot 3 = Wo

// ---------------------------------------------------------------------------
// PTX helpers
// ---------------------------------------------------------------------------
__device__ __forceinline__ uint32_t smem_u32(const void* p) {
    uint32_t a;
    asm("{ .reg .u64 t; cvta.to.shared.u64 t, %1; cvt.u32.u64 %0, t; }"
        : "=r"(a) : "l"(p));
    return a;
}

#define CPASYNC16(s, g) \
    asm volatile("cp.async.cg.shared.global [%0], [%1], 16;" \
                 :: "r"(s), "l"(g) : "memory")
#define CPCOMMIT() asm volatile("cp.async.commit_group;" ::: "memory")
#define CPWAIT3()  asm volatile("cp.async.wait_group 3;" ::: "memory")

__device__ __forceinline__ void ldsm4(uint32_t* r, uint32_t a) {
    asm volatile("ldmatrix.sync.aligned.m8n8.x4.shared.b16 {%0,%1,%2,%3}, [%4];"
        : "=r"(r[0]), "=r"(r[1]), "=r"(r[2]), "=r"(r[3]) : "r"(a));
}
__device__ __forceinline__ void ldsm2(uint32_t* r, uint32_t a) {
    asm volatile("ldmatrix.sync.aligned.m8n8.x2.shared.b16 {%0,%1}, [%2];"
        : "=r"(r[0]), "=r"(r[1]) : "r"(a));
}
__device__ __forceinline__ void mma16816(float* c, const uint32_t* a, const uint32_t* b) {
    asm volatile("mma.sync.aligned.m16n8k16.row.col.f32.f16.f16.f32 "
        "{%0,%1,%2,%3}, {%4,%5,%6,%7}, {%8,%9}, {%0,%1,%2,%3};"
        : "+f"(c[0]), "+f"(c[1]), "+f"(c[2]), "+f"(c[3])
        : "r"(a[0]), "r"(a[1]), "r"(a[2]), "r"(a[3]), "r"(b[0]), "r"(b[1]));
}

// ---------------------------------------------------------------------------
// split_input3: fp32 -> fp16, batched over z = {q,k,v}
// ---------------------------------------------------------------------------
__global__ void __launch_bounds__(256) split_input3(
    const float* __restrict__ Xq, const float* __restrict__ Xk,
    const float* __restrict__ Xv, int n4)
{
    int z = blockIdx.y;
    const float* X = (z == 0) ? Xq : (z == 1) ? Xk : Xv;
    __half* out = g_Ah + (size_t)z * MROWS * DM;
    int idx = blockIdx.x * 256 + threadIdx.x;
    if (idx >= n4) return;
    float4 x = ((const float4*)X)[idx];
    __half2* op = (__half2*)out;
    op[idx * 2 + 0] = __floats2half2_rn(x.x, x.y);
    op[idx * 2 + 1] = __floats2half2_rn(x.z, x.w);
}

// transpose4: W[k][n] fp32 -> Wt fp16 [n][k], batched over 4 weights
__global__ void __launch_bounds__(256) transpose4(
    const float* __restrict__ W0, const float* __restrict__ W1,
    const float* __restrict__ W2, const float* __restrict__ W3)
{
    __shared__ float t[32][33];
    int z = blockIdx.z;
    const float* W = (z == 0) ? W0 : (z == 1) ? W1 : (z == 2) ? W2 : W3;
    __half* hi = g_W + (size_t)z * DM * DM;
    int bx = blockIdx.x * 32;   // n base
    int by = blockIdx.y * 32;   // k base
    int tx = threadIdx.x & 31;
    int ty = threadIdx.x >> 5;  // 0..7
#pragma unroll
    for (int i = 0; i < 4; i++) {
        int k = by + ty + i * 8;
        t[ty + i * 8][tx] = W[(size_t)k * DM + bx + tx];
    }
    __syncthreads();
#pragma unroll
    for (int i = 0; i < 4; i++) {
        int n = bx + ty + i * 8;
        int k = by + tx;
        hi[(size_t)n * DM + k] = __float2half_rn(t[tx][ty + i * 8]);
    }
}

// ---------------------------------------------------------------------------
// fp16 single-term GEMM: C = A @ W + bias (+elu+1)
// BM=BN=128, BK=32, 256 threads, warp tile 64x32, cp.async 4-stage, 2 CTA/SM.
// ---------------------------------------------------------------------------
#define ARR 10240            // 128 rows * 80B
#define STG (2 * ARR)        // 20480 per stage
#define NSTAGE 4
#define GEMM_SMEM (NSTAGE * STG)  // 81920

__device__ __forceinline__ void load_stage(
    uint32_t sbase, int tid, int k0,
    const __half* pA, const __half* pW)
{
#pragma unroll
    for (int rep = 0; rep < 2; rep++) {
        int l = rep * 256 + tid;        // 0..511
        int row = l >> 2;               // 0..127
        int ch = l & 3;                 // 0..3 (16B chunks)
        uint32_t so = sbase + (uint32_t)row * 80 + ch * 16;
        size_t go = (size_t)row * DM + k0 + ch * 8;
        CPASYNC16(so + 0 * ARR, pA + go);
        CPASYNC16(so + 1 * ARR, pW + go);
    }
}

__global__ void __launch_bounds__(256, 2) gemm_f16(
    const __half* __restrict__ Ah, const __half* __restrict__ W,
    const float* __restrict__ b0, const float* __restrict__ b1,
    const float* __restrict__ b2,
    float* __restrict__ C0,
    __half* __restrict__ H0, __half* __restrict__ H1, __half* __restrict__ H2,
    int actMask, int halfMask)
{
    extern __shared__ char smem[];
    const uint32_t sb = smem_u32(smem);
    const int z = blockIdx.z;
    const int tid = threadIdx.x;
    const int wid = tid >> 5;
    const int lid = tid & 31;
    const int rowBase = blockIdx.y * 128;
    const int colBase = blockIdx.x * 128;
    const int warpM = (wid >> 2) * 64;
    const int warpN = (wid & 3) * 32;

    const float* bias = (z == 0) ? b0 : (z == 1) ? b1 : b2;
    const int act = (actMask >> z) & 1;
    const int hout = (halfMask >> z) & 1;

    const __half* pA = Ah + (size_t)z * MROWS * DM + (size_t)rowBase * DM;
    const __half* pW = W  + (size_t)z * DM * DM + (size_t)colBase * DM;

    float acc[4][4][4];
#pragma unroll
    for (int i = 0; i < 4; i++)
#pragma unroll
        for (int j = 0; j < 4; j++)
#pragma unroll
            for (int e = 0; e < 4; e++) acc[i][j][e] = 0.f;

    // prologue: stages 0, 1, 2
    load_stage(sb + 0 * STG, tid, 0, pA, pW);
    CPCOMMIT();
    load_stage(sb + 1 * STG, tid, 32, pA, pW);
    CPCOMMIT();
    load_stage(sb + 2 * STG, tid, 64, pA, pW);
    CPCOMMIT();

    const int aRow = warpM + (lid & 15);
    const uint32_t aCol = ((lid >> 4) & 1) * 16;
    const int bRow = warpN + (lid & 7);
    const uint32_t bCol = ((lid >> 3) & 1) * 16;

    for (int c = 0; c < 32; c++) {
        if (c + 3 < 32)
            load_stage(sb + ((c + 3) % NSTAGE) * STG, tid, (c + 3) * 32, pA, pW);
        CPCOMMIT();          // possibly-empty group keeps the count uniform
        CPWAIT3();           // <=3 pending -> stage c complete
        __syncthreads();

        const uint32_t stage = sb + (c % NSTAGE) * STG;
#pragma unroll
        for (int kk = 0; kk < 2; kk++) {
            const uint32_t aOff = (uint32_t)kk * 32 + aCol;
            const uint32_t bOff = (uint32_t)kk * 32 + bCol;
            uint32_t fB[4][2];
#pragma unroll
            for (int ni = 0; ni < 4; ni++)
                ldsm2(fB[ni], stage + (uint32_t)(bRow + ni * 8) * 80 + bOff + 1 * ARR);
#pragma unroll
            for (int mi = 0; mi < 4; mi++) {
                uint32_t fA[4];
                ldsm4(fA, stage + (uint32_t)(aRow + mi * 16) * 80 + aOff);
#pragma unroll
                for (int ni = 0; ni < 4; ni++)
                    mma16816(acc[mi][ni], fA, fB[ni]);
            }
        }
        __syncthreads();
    }

    // epilogue
    __half* H = (z == 0) ? H0 : (z == 1) ? H1 : H2;
#pragma unroll
    for (int mi = 0; mi < 4; mi++) {
        int r0 = rowBase + warpM + mi * 16 + (lid >> 2);
#pragma unroll
        for (int ni = 0; ni < 4; ni++) {
            int col = colBase + warpN + ni * 8 + (lid & 3) * 2;
            float2 b2v = *(const float2*)(bias + col);
            float v0 = acc[mi][ni][0] + b2v.x;
            float v1 = acc[mi][ni][1] + b2v.y;
            float v2 = acc[mi][ni][2] + b2v.x;
            float v3 = acc[mi][ni][3] + b2v.y;
            if (act) {
                v0 = (v0 > 0.f) ? (v0 + 1.f) : expf(v0);
                v1 = (v1 > 0.f) ? (v1 + 1.f) : expf(v1);
                v2 = (v2 > 0.f) ? (v2 + 1.f) : expf(v2);
                v3 = (v3 > 0.f) ? (v3 + 1.f) : expf(v3);
            }
            if (hout) {
                *(__half2*)(H + (size_t)r0 * DM + col)       = __floats2half2_rn(v0, v1);
                *(__half2*)(H + (size_t)(r0 + 8) * DM + col) = __floats2half2_rn(v2, v3);
            } else {
                float2 o0; o0.x = v0; o0.y = v1;
                float2 o1; o1.x = v2; o1.y = v3;
                *(float2*)(C0 + (size_t)r0 * DM + col) = o0;
                *(float2*)(C0 + (size_t)(r0 + 8) * DM + col) = o1;
            }
        }
    }
}

// ---------------------------------------------------------------------------
// Attention kernels (FFMA; q read as fp16, converted once at smem fill)
// ---------------------------------------------------------------------------
__global__ void __launch_bounds__(256) chunk_sums_kernel()
{
    const int c = blockIdx.x;
    const int nh = blockIdx.y;
    const int n = nh >> 4;
    const int h = nh & 15;
    const int tid = threadIdx.x;

    __shared__ float Ks[64][68];
    __shared__ float Vs[64][68];
    __shared__ float qsum[4][72];

    const size_t rowbase = ((size_t)(n * LSEQ + c * CH)) * DM + h * HD;

    // qp partial column sums from fp16 q
    {
        int col = tid & 63;
        int qtr = tid >> 6;     // 0..3
        float s = 0.f;
        const __half* qb = g_qh + rowbase + (size_t)(qtr * 16) * DM + col;
#pragma unroll
        for (int i = 0; i < 16; i++)
            s += __half2float(qb[(size_t)i * DM]);
        qsum[qtr][col] = s;
    }

#pragma unroll
    for (int rep = 0; rep < 2; rep++) {
        int idx = rep * 256 + tid;      // 0..511
        int i  = idx >> 3;              // row
        int j8 = (idx & 7) * 8;         // col base
        uint4 ku = *(const uint4*)(g_kh + rowbase + (size_t)i * DM + j8);
        uint4 vu = *(const uint4*)(g_vh + rowbase + (size_t)i * DM + j8);
        const __half2* kh2 = (const __half2*)&ku;
        const __half2* vh2 = (const __half2*)&vu;
#pragma unroll
        for (int t = 0; t < 4; t++) {
            float2 kf = __half22float2(kh2[t]);
            float2 vf = __half22float2(vh2[t]);
            Ks[i][j8 + t * 2 + 0] = kf.x;
            Ks[i][j8 + t * 2 + 1] = kf.y;
            Vs[i][j8 + t * 2 + 0] = vf.x;
            Vs[i][j8 + t * 2 + 1] = vf.y;
        }
    }
    __syncthreads();

    const int td = (tid >> 4) * 4;
    const int tk = (tid & 15) * 4;
    float acc[4][4];
#pragma unroll
    for (int a = 0; a < 4; a++)
#pragma unroll
        for (int b = 0; b < 4; b++) acc[a][b] = 0.f;

    for (int i = 0; i < 64; i++) {
        float ka[4];
        ka[0] = Ks[i][td + 0]; ka[1] = Ks[i][td + 1];
        ka[2] = Ks[i][td + 2]; ka[3] = Ks[i][td + 3];
        float4 vv = *(const float4*)&Vs[i][tk];
        float vb[4] = {vv.x, vv.y, vv.z, vv.w};
#pragma unroll
        for (int a = 0; a < 4; a++)
#pragma unroll
            for (int b = 0; b < 4; b++)
                acc[a][b] = fmaf(ka[a], vb[b], acc[a][b]);
    }

    float* Sp = g_S + ((size_t)nh * NC + c) * (HD * HD);
#pragma unroll
    for (int a = 0; a < 4; a++) {
        float4 o; o.x=acc[a][0]; o.y=acc[a][1]; o.z=acc[a][2]; o.w=acc[a][3];
        *(float4*)&Sp[(td + a) * HD + tk] = o;
    }

    if (tid < 64) {
        float s = qsum[0][tid] + qsum[1][tid] + qsum[2][tid] + qsum[3][tid];
        g_qs[((size_t)nh * NC + c) * HD + tid] = s;
    }
}

// Parallel prefix: grid (NH, 8), 256 threads; each thread scans 2 elements.
__global__ void __launch_bounds__(256) prefix_kernel()
{
    const int nh = blockIdx.x;
    const int seg = blockIdx.y;     // 0..7
    const int tid = threadIdx.x;
    const int e0 = seg * 512 + tid;

    float r0 = 0.f, r1 = 0.f;
    for (int c = 0; c < NC; c++) {
        float* Sp = g_S + ((size_t)nh * NC + c) * (HD * HD);
        float t0 = Sp[e0];       Sp[e0] = r0;       r0 += t0;
        float t1 = Sp[e0 + 256]; Sp[e0 + 256] = r1; r1 += t1;
    }

    if (seg == 0 && tid < 64) {
        float r = 0.f;
        for (int c = 0; c < NC; c++) {
            float* qp = g_qs + ((size_t)nh * NC + c) * HD + tid;
            float t = *qp;
            *qp = r;
            r += t;
        }
    }
}

// chunk_out: O = (tril(Qp Kp^T) V + Qp P) / Z, fp16 out into g_Ah[0].
#define TS (64 * 68)
#define CO_SMEM (4 * TS * 4)   // 69632 bytes
__global__ void __launch_bounds__(256, 2) chunk_out_kernel()
{
    extern __shared__ float fsm[];
    float* Qs = fsm;            // [i][d]
    float* Kt = fsm + TS;       // [d][i]  -> Zc later
    float* Vs = fsm + 2 * TS;   // [j][k]
    float* Ps = fsm + 3 * TS;   // [d][k]  -> As later

    const int c = blockIdx.x;
    const int nh = blockIdx.y;
    const int n = nh >> 4;
    const int h = nh & 15;
    const int tid = threadIdx.x;

    const size_t rowbase = ((size_t)(n * LSEQ + c * CH)) * DM + h * HD;
    const float* Sp = g_S + ((size_t)nh * NC + c) * (HD * HD);

    // P (fp32)
#pragma unroll
    for (int rep = 0; rep < 4; rep++) {
        int idx = rep * 256 + tid;
        float4 p = *(const float4*)(Sp + idx * 4);
        int d = (idx * 4) >> 6;
        int kk = (idx * 4) & 63;
        *(float4*)&Ps[d * 68 + kk] = p;
    }
    // Q (fp16 -> fp32 smem), K (fp16, transposed), V (fp16)
#pragma unroll
    for (int rep = 0; rep < 2; rep++) {
        int idx = rep * 256 + tid;      // 0..511
        int i  = idx >> 3;
        int j8 = (idx & 7) * 8;
        uint4 qu = *(const uint4*)(g_qh + rowbase + (size_t)i * DM + j8);
        uint4 ku = *(const uint4*)(g_kh + rowbase + (size_t)i * DM + j8);
        uint4 vu = *(const uint4*)(g_vh + rowbase + (size_t)i * DM + j8);
        const __half2* qh2 = (const __half2*)&qu;
        const __half2* kh2 = (const __half2*)&ku;
        const __half2* vh2 = (const __half2*)&vu;
#pragma unroll
        for (int t = 0; t < 4; t++) {
            float2 qf = __half22float2(qh2[t]);
            float2 kf = __half22float2(kh2[t]);
            float2 vf = __half22float2(vh2[t]);
            Qs[i * 68 + j8 + t * 2 + 0] = qf.x;
            Qs[i * 68 + j8 + t * 2 + 1] = qf.y;
            Kt[(j8 + t * 2 + 0) * 68 + i] = kf.x;
            Kt[(j8 + t * 2 + 1) * 68 + i] = kf.y;
            Vs[i * 68 + j8 + t * 2 + 0] = vf.x;
            Vs[i * 68 + j8 + t * 2 + 1] = vf.y;
        }
    }
    __syncthreads();

    const int ti = (tid >> 4) * 4;
    const int tj = (tid & 15) * 4;

    float accO[4][4];
    float at[4][4];
#pragma unroll
    for (int a = 0; a < 4; a++)
#pragma unroll
        for (int b = 0; b < 4; b++) { accO[a][b] = 0.f; at[a][b] = 0.f; }

    for (int d = 0; d < 64; d++) {
        float qa[4];
        qa[0] = Qs[(ti + 0) * 68 + d]; qa[1] = Qs[(ti + 1) * 68 + d];
        qa[2] = Qs[(ti + 2) * 68 + d]; qa[3] = Qs[(ti + 3) * 68 + d];
        float4 pp = *(const float4*)&Ps[d * 68 + tj];
        float4 kb = *(const float4*)&Kt[d * 68 + tj];
        float pb[4] = {pp.x, pp.y, pp.z, pp.w};
        float kv[4] = {kb.x, kb.y, kb.z, kb.w};
#pragma unroll
        for (int a = 0; a < 4; a++)
#pragma unroll
            for (int b = 0; b < 4; b++) {
                accO[a][b] = fmaf(qa[a], pb[b], accO[a][b]);
                at[a][b]   = fmaf(qa[a], kv[b], at[a][b]);
            }
    }
#pragma unroll
    for (int a = 0; a < 4; a++)
#pragma unroll
        for (int b = 0; b < 4; b++)
            if (tj + b > ti + a) at[a][b] = 0.f;

    __syncthreads();

    float* As = Ps;
    float* Zc = Kt;
#pragma unroll
    for (int a = 0; a < 4; a++) {
        float4 o; o.x = at[a][0]; o.y = at[a][1]; o.z = at[a][2]; o.w = at[a][3];
        *(float4*)&As[(ti + a) * 68 + tj] = o;
    }
    if (tid < 64) {
        float z = g_qs[((size_t)nh * NC + c) * HD + tid];
        for (int i = 0; i < 64; i++) {
            z += Qs[i * 68 + tid];
            Zc[i * 68 + tid] = z;
        }
    }
    __syncthreads();

    for (int j = 0; j < 64; j++) {
        float aa[4];
        aa[0] = As[(ti + 0) * 68 + j]; aa[1] = As[(ti + 1) * 68 + j];
        aa[2] = As[(ti + 2) * 68 + j]; aa[3] = As[(ti + 3) * 68 + j];
        float4 vv = *(const float4*)&Vs[j * 68 + tj];
        float vb[4] = {vv.x, vv.y, vv.z, vv.w};
#pragma unroll
        for (int a = 0; a < 4; a++)
#pragma unroll
            for (int b = 0; b < 4; b++)
                accO[a][b] = fmaf(aa[a], vb[b], accO[a][b]);
    }

#pragma unroll
    for (int a = 0; a < 4; a++) {
        float4 z4 = *(const float4*)&Zc[(ti + a) * 68 + tj];
        __half2 h01 = __floats2half2_rn(accO[a][0] / z4.x, accO[a][1] / z4.y);
        __half2 h23 = __floats2half2_rn(accO[a][2] / z4.z, accO[a][3] / z4.w);
        size_t eo = rowbase + (size_t)(ti + a) * DM + tj;
        *(__half2*)(g_Ah + eo)     = h01;
        *(__half2*)(g_Ah + eo + 2) = h23;
    }
}

// ---------------------------------------------------------------------------
extern "C" void kernel_launch(void* const* d_in, const int* in_sizes, int n_in,
                              void* d_out, int out_size)
{
    const float* queries = (const float*)d_in[0];
    const float* keys    = (const float*)d_in[1];
    const float* values  = (const float*)d_in[2];
    const float* Wq = (const float*)d_in[3];
    const float* bq = (const float*)d_in[4];
    const float* Wk = (const float*)d_in[5];
    const float* bk = (const float*)d_in[6];
    const float* Wv = (const float*)d_in[7];
    const float* bv = (const float*)d_in[8];
    const float* Wo = (const float*)d_in[9];
    const float* bo = (const float*)d_in[10];
    float* out = (float*)d_out;

    __half* qh; cudaGetSymbolAddress((void**)&qh,  g_qh);
    __half* kh; cudaGetSymbolAddress((void**)&kh,  g_kh);
    __half* vh; cudaGetSymbolAddress((void**)&vh,  g_vh);
    __half* ah; cudaGetSymbolAddress((void**)&ah,  g_Ah);
    __half* w;  cudaGetSymbolAddress((void**)&w,   g_W);

    static bool attrSet = false;
    if (!attrSet) {
        cudaFuncSetAttribute(gemm_f16, cudaFuncAttributeMaxDynamicSharedMemorySize,
                             GEMM_SMEM);
        cudaFuncSetAttribute(chunk_out_kernel,
                             cudaFuncAttributeMaxDynamicSharedMemorySize,
                             CO_SMEM);
        attrSet = true;
    }

    const int splitBlocks = (MROWS * DM / 4 + 255) / 256;

    // Split inputs and all 4 weights (batched, single-term fp16)
    split_input3<<<dim3(splitBlocks, 3), 256>>>(queries, keys, values,
                                                MROWS * DM / 4);
    transpose4<<<dim3(DM / 32, DM / 32, 4), 256>>>(Wq, Wk, Wv, Wo);

    // Fused Q/K/V projections: all outputs fp16 (q/k with elu+1)
    gemm_f16<<<dim3(DM / 128, MROWS / 128, 3), 256, GEMM_SMEM>>>(
        ah, w, bq, bk, bv, nullptr, qh, kh, vh, 0x3, 0x7);

    // Chunked causal linear attention
    dim3 chunkGrid(NC, NH);
    chunk_sums_kernel<<<chunkGrid, 256>>>();
    prefix_kernel<<<dim3(NH, 8), 256>>>();
    chunk_out_kernel<<<chunkGrid, 256, CO_SMEM>>>();

    // Output projection: att (slot 0 of g_Ah) @ Wo (slot 3) + bo -> fp32 out
    gemm_f16<<<dim3(DM / 128, MROWS / 128, 1), 256, GEMM_SMEM>>>(
        ah, w + 3 * (size_t)DM * DM, bo, bo, bo, out, qh, kh, vh, 0x0, 0x0);
}

// round 15
// speedup vs baseline: 1.0429x; 1.0429x over previous
#include <cuda_runtime.h>
#include <cuda_fp16.h>
#include <math.h>
#include <cstdint>

// Problem constants
#define NB 4
#define LSEQ 2048
#define DM 1024
#define NHEAD 16
#define HD 64
#define MROWS (NB * LSEQ)   // 8192
#define CH 64
#define NC (LSEQ / CH)      // 32
#define NH (NB * NHEAD)     // 64

// Scratch (device globals; no allocation allowed)
__device__ __half g_qh[MROWS * DM];         // elu(q)+1 fp16
__device__ __half g_kh[MROWS * DM];         // elu(k)+1 fp16
__device__ __half g_vh[MROWS * DM];         // v projection fp16
__device__ float g_S [NH * NC * HD * HD];
__device__ float g_qs[NH * NC * HD];

// fp16 GEMM operand scratch
__device__ __half g_Ah[3 * MROWS * DM];     // q,k,v inputs (att reuses slot 0)
__device__ __half g_W [4 * DM * DM];        // transposed [n][k]; slot 3 = Wo

// ---------------------------------------------------------------------------
// PTX helpers
// ---------------------------------------------------------------------------
__device__ __forceinline__ uint32_t smem_u32(const void* p) {
    uint32_t a;
    asm("{ .reg .u64 t; cvta.to.shared.u64 t, %1; cvt.u32.u64 %0, t; }"
        : "=r"(a) : "l"(p));
    return a;
}

#define CPASYNC16(s, g) \
    asm volatile("cp.async.cg.shared.global [%0], [%1], 16;" \
                 :: "r"(s), "l"(g) : "memory")
#define CPCOMMIT() asm volatile("cp.async.commit_group;" ::: "memory")
#define CPWAIT2()  asm volatile("cp.async.wait_group 2;" ::: "memory")

__device__ __forceinline__ void ldsm4(uint32_t* r, uint32_t a) {
    asm volatile("ldmatrix.sync.aligned.m8n8.x4.shared.b16 {%0,%1,%2,%3}, [%4];"
        : "=r"(r[0]), "=r"(r[1]), "=r"(r[2]), "=r"(r[3]) : "r"(a));
}
__device__ __forceinline__ void ldsm2(uint32_t* r, uint32_t a) {
    asm volatile("ldmatrix.sync.aligned.m8n8.x2.shared.b16 {%0,%1}, [%2];"
        : "=r"(r[0]), "=r"(r[1]) : "r"(a));
}
__device__ __forceinline__ void mma16816(float* c, const uint32_t* a, const uint32_t* b) {
    asm volatile("mma.sync.aligned.m16n8k16.row.col.f32.f16.f16.f32 "
        "{%0,%1,%2,%3}, {%4,%5,%6,%7}, {%8,%9}, {%0,%1,%2,%3};"
        : "+f"(c[0]), "+f"(c[1]), "+f"(c[2]), "+f"(c[3])
        : "r"(a[0]), "r"(a[1]), "r"(a[2]), "r"(a[3]), "r"(b[0]), "r"(b[1]));
}

// ---------------------------------------------------------------------------
// split_input3: fp32 -> fp16, batched over z = {q,k,v}
// ---------------------------------------------------------------------------
__global__ void __launch_bounds__(256) split_input3(
    const float* __restrict__ Xq, const float* __restrict__ Xk,
    const float* __restrict__ Xv, int n4)
{
    int z = blockIdx.y;
    const float* X = (z == 0) ? Xq : (z == 1) ? Xk : Xv;
    __half* out = g_Ah + (size_t)z * MROWS * DM;
    int idx = blockIdx.x * 256 + threadIdx.x;
    if (idx >= n4) return;
    float4 x = ((const float4*)X)[idx];
    __half2* op = (__half2*)out;
    op[idx * 2 + 0] = __floats2half2_rn(x.x, x.y);
    op[idx * 2 + 1] = __floats2half2_rn(x.z, x.w);
}

// transpose4: W[k][n] fp32 -> Wt fp16 [n][k], batched over 4 weights
__global__ void __launch_bounds__(256) transpose4(
    const float* __restrict__ W0, const float* __restrict__ W1,
    const float* __restrict__ W2, const float* __restrict__ W3)
{
    __shared__ float t[32][33];
    int z = blockIdx.z;
    const float* W = (z == 0) ? W0 : (z == 1) ? W1 : (z == 2) ? W2 : W3;
    __half* hi = g_W + (size_t)z * DM * DM;
    int bx = blockIdx.x * 32;   // n base
    int by = blockIdx.y * 32;   // k base
    int tx = threadIdx.x & 31;
    int ty = threadIdx.x >> 5;  // 0..7
#pragma unroll
    for (int i = 0; i < 4; i++) {
        int k = by + ty + i * 8;
        t[ty + i * 8][tx] = W[(size_t)k * DM + bx + tx];
    }
    __syncthreads();
#pragma unroll
    for (int i = 0; i < 4; i++) {
        int n = bx + ty + i * 8;
        int k = by + tx;
        hi[(size_t)n * DM + k] = __float2half_rn(t[tx][ty + i * 8]);
    }
}

// ---------------------------------------------------------------------------
// fp16 single-term GEMM: C = A @ W + bias (+elu+1)
// BM=BN=128, BK=32, 256 threads, warp tile 64x32, cp.async 3-stage, 2 CTA/SM.
// ---------------------------------------------------------------------------
#define ARR 10240            // 128 rows * 80B
#define STG (2 * ARR)        // 20480 per stage
#define NSTAGE 3
#define GEMM_SMEM (NSTAGE * STG)  // 61440

__device__ __forceinline__ void load_stage(
    uint32_t sbase, int tid, int k0,
    const __half* pA, const __half* pW)
{
#pragma unroll
    for (int rep = 0; rep < 2; rep++) {
        int l = rep * 256 + tid;        // 0..511
        int row = l >> 2;               // 0..127
        int ch = l & 3;                 // 0..3 (16B chunks)
        uint32_t so = sbase + (uint32_t)row * 80 + ch * 16;
        size_t go = (size_t)row * DM + k0 + ch * 8;
        CPASYNC16(so + 0 * ARR, pA + go);
        CPASYNC16(so + 1 * ARR, pW + go);
    }
}

__global__ void __launch_bounds__(256, 2) gemm_f16(
    const __half* __restrict__ Ah, const __half* __restrict__ W,
    const float* __restrict__ b0, const float* __restrict__ b1,
    const float* __restrict__ b2,
    float* __restrict__ C0,
    __half* __restrict__ H0, __half* __restrict__ H1, __half* __restrict__ H2,
    int actMask, int halfMask)
{
    extern __shared__ char smem[];
    const uint32_t sb = smem_u32(smem);
    const int z = blockIdx.z;
    const int tid = threadIdx.x;
    const int wid = tid >> 5;
    const int lid = tid & 31;
    const int rowBase = blockIdx.y * 128;
    const int colBase = blockIdx.x * 128;
    const int warpM = (wid >> 2) * 64;
    const int warpN = (wid & 3) * 32;

    const float* bias = (z == 0) ? b0 : (z == 1) ? b1 : b2;
    const int act = (actMask >> z) & 1;
    const int hout = (halfMask >> z) & 1;

    const __half* pA = Ah + (size_t)z * MROWS * DM + (size_t)rowBase * DM;
    const __half* pW = W  + (size_t)z * DM * DM + (size_t)colBase * DM;

    float acc[4][4][4];
#pragma unroll
    for (int i = 0; i < 4; i++)
#pragma unroll
        for (int j = 0; j < 4; j++)
#pragma unroll
            for (int e = 0; e < 4; e++) acc[i][j][e] = 0.f;

    // prologue: stages 0, 1
    load_stage(sb + 0 * STG, tid, 0, pA, pW);
    CPCOMMIT();
    load_stage(sb + 1 * STG, tid, 32, pA, pW);
    CPCOMMIT();

    const int aRow = warpM + (lid & 15);
    const uint32_t aCol = ((lid >> 4) & 1) * 16;
    const int bRow = warpN + (lid & 7);
    const uint32_t bCol = ((lid >> 3) & 1) * 16;

    for (int c = 0; c < 32; c++) {
        if (c + 2 < 32)
            load_stage(sb + ((c + 2) % NSTAGE) * STG, tid, (c + 2) * 32, pA, pW);
        CPCOMMIT();          // possibly-empty group keeps the count uniform
        CPWAIT2();           // <=2 pending -> stage c complete
        __syncthreads();

        const uint32_t stage = sb + (c % NSTAGE) * STG;
#pragma unroll
        for (int kk = 0; kk < 2; kk++) {
            const uint32_t aOff = (uint32_t)kk * 32 + aCol;
            const uint32_t bOff = (uint32_t)kk * 32 + bCol;
            uint32_t fB[4][2];
#pragma unroll
            for (int ni = 0; ni < 4; ni++)
                ldsm2(fB[ni], stage + (uint32_t)(bRow + ni * 8) * 80 + bOff + 1 * ARR);
#pragma unroll
            for (int mi = 0; mi < 4; mi++) {
                uint32_t fA[4];
                ldsm4(fA, stage + (uint32_t)(aRow + mi * 16) * 80 + aOff);
#pragma unroll
                for (int ni = 0; ni < 4; ni++)
                    mma16816(acc[mi][ni], fA, fB[ni]);
            }
        }
        __syncthreads();
    }

    // epilogue
    __half* H = (z == 0) ? H0 : (z == 1) ? H1 : H2;
#pragma unroll
    for (int mi = 0; mi < 4; mi++) {
        int r0 = rowBase + warpM + mi * 16 + (lid >> 2);
#pragma unroll
        for (int ni = 0; ni < 4; ni++) {
            int col = colBase + warpN + ni * 8 + (lid & 3) * 2;
            float2 b2v = *(const float2*)(bias + col);
            float v0 = acc[mi][ni][0] + b2v.x;
            float v1 = acc[mi][ni][1] + b2v.y;
            float v2 = acc[mi][ni][2] + b2v.x;
            float v3 = acc[mi][ni][3] + b2v.y;
            if (act) {
                v0 = (v0 > 0.f) ? (v0 + 1.f) : expf(v0);
                v1 = (v1 > 0.f) ? (v1 + 1.f) : expf(v1);
                v2 = (v2 > 0.f) ? (v2 + 1.f) : expf(v2);
                v3 = (v3 > 0.f) ? (v3 + 1.f) : expf(v3);
            }
            if (hout) {
                *(__half2*)(H + (size_t)r0 * DM + col)       = __floats2half2_rn(v0, v1);
                *(__half2*)(H + (size_t)(r0 + 8) * DM + col) = __floats2half2_rn(v2, v3);
            } else {
                float2 o0; o0.x = v0; o0.y = v1;
                float2 o1; o1.x = v2; o1.y = v3;
                *(float2*)(C0 + (size_t)r0 * DM + col) = o0;
                *(float2*)(C0 + (size_t)(r0 + 8) * DM + col) = o1;
            }
        }
    }
}

// ---------------------------------------------------------------------------
// Attention kernels (FFMA; q read as fp16, converted once at smem fill)
// ---------------------------------------------------------------------------
__global__ void __launch_bounds__(256) chunk_sums_kernel()
{
    const int c = blockIdx.x;
    const int nh = blockIdx.y;
    const int n = nh >> 4;
    const int h = nh & 15;
    const int tid = threadIdx.x;

    __shared__ float Ks[64][68];
    __shared__ float Vs[64][68];
    __shared__ float qsum[4][72];

    const size_t rowbase = ((size_t)(n * LSEQ + c * CH)) * DM + h * HD;

    // qp partial column sums from fp16 q
    {
        int col = tid & 63;
        int qtr = tid >> 6;     // 0..3
        float s = 0.f;
        const __half* qb = g_qh + rowbase + (size_t)(qtr * 16) * DM + col;
#pragma unroll
        for (int i = 0; i < 16; i++)
            s += __half2float(qb[(size_t)i * DM]);
        qsum[qtr][col] = s;
    }

#pragma unroll
    for (int rep = 0; rep < 2; rep++) {
        int idx = rep * 256 + tid;      // 0..511
        int i  = idx >> 3;              // row
        int j8 = (idx & 7) * 8;         // col base
        uint4 ku = *(const uint4*)(g_kh + rowbase + (size_t)i * DM + j8);
        uint4 vu = *(const uint4*)(g_vh + rowbase + (size_t)i * DM + j8);
        const __half2* kh2 = (const __half2*)&ku;
        const __half2* vh2 = (const __half2*)&vu;
#pragma unroll
        for (int t = 0; t < 4; t++) {
            float2 kf = __half22float2(kh2[t]);
            float2 vf = __half22float2(vh2[t]);
            Ks[i][j8 + t * 2 + 0] = kf.x;
            Ks[i][j8 + t * 2 + 1] = kf.y;
            Vs[i][j8 + t * 2 + 0] = vf.x;
            Vs[i][j8 + t * 2 + 1] = vf.y;
        }
    }
    __syncthreads();

    const int td = (tid >> 4) * 4;
    const int tk = (tid & 15) * 4;
    float acc[4][4];
#pragma unroll
    for (int a = 0; a < 4; a++)
#pragma unroll
        for (int b = 0; b < 4; b++) acc[a][b] = 0.f;

    for (int i = 0; i < 64; i++) {
        float ka[4];
        ka[0] = Ks[i][td + 0]; ka[1] = Ks[i][td + 1];
        ka[2] = Ks[i][td + 2]; ka[3] = Ks[i][td + 3];
        float4 vv = *(const float4*)&Vs[i][tk];
        float vb[4] = {vv.x, vv.y, vv.z, vv.w};
#pragma unroll
        for (int a = 0; a < 4; a++)
#pragma unroll
            for (int b = 0; b < 4; b++)
                acc[a][b] = fmaf(ka[a], vb[b], acc[a][b]);
    }

    float* Sp = g_S + ((size_t)nh * NC + c) * (HD * HD);
#pragma unroll
    for (int a = 0; a < 4; a++) {
        float4 o; o.x=acc[a][0]; o.y=acc[a][1]; o.z=acc[a][2]; o.w=acc[a][3];
        *(float4*)&Sp[(td + a) * HD + tk] = o;
    }

    if (tid < 64) {
        float s = qsum[0][tid] + qsum[1][tid] + qsum[2][tid] + qsum[3][tid];
        g_qs[((size_t)nh * NC + c) * HD + tid] = s;
    }
}

// Parallel prefix: grid (NH, 8), 256 threads; each thread scans 2 elements.
__global__ void __launch_bounds__(256) prefix_kernel()
{
    const int nh = blockIdx.x;
    const int seg = blockIdx.y;     // 0..7
    const int tid = threadIdx.x;
    const int e0 = seg * 512 + tid;

    float r0 = 0.f, r1 = 0.f;
    for (int c = 0; c < NC; c++) {
        float* Sp = g_S + ((size_t)nh * NC + c) * (HD * HD);
        float t0 = Sp[e0];       Sp[e0] = r0;       r0 += t0;
        float t1 = Sp[e0 + 256]; Sp[e0 + 256] = r1; r1 += t1;
    }

    if (seg == 0 && tid < 64) {
        float r = 0.f;
        for (int c = 0; c < NC; c++) {
            float* qp = g_qs + ((size_t)nh * NC + c) * HD + tid;
            float t = *qp;
            *qp = r;
            r += t;
        }
    }
}

// chunk_out: O = (tril(Qp Kp^T) V + Qp P) / Z, fp16 out into g_Ah[0].
#define TS (64 * 68)
#define CO_SMEM (4 * TS * 4)   // 69632 bytes
__global__ void __launch_bounds__(256, 2) chunk_out_kernel()
{
    extern __shared__ float fsm[];
    float* Qs = fsm;            // [i][d]
    float* Kt = fsm + TS;       // [d][i]  -> Zc later
    float* Vs = fsm + 2 * TS;   // [j][k]
    float* Ps = fsm + 3 * TS;   // [d][k]  -> As later

    const int c = blockIdx.x;
    const int nh = blockIdx.y;
    const int n = nh >> 4;
    const int h = nh & 15;
    const int tid = threadIdx.x;

    const size_t rowbase = ((size_t)(n * LSEQ + c * CH)) * DM + h * HD;
    const float* Sp = g_S + ((size_t)nh * NC + c) * (HD * HD);

    // P (fp32)
#pragma unroll
    for (int rep = 0; rep < 4; rep++) {
        int idx = rep * 256 + tid;
        float4 p = *(const float4*)(Sp + idx * 4);
        int d = (idx * 4) >> 6;
        int kk = (idx * 4) & 63;
        *(float4*)&Ps[d * 68 + kk] = p;
    }
    // Q (fp16 -> fp32 smem), K (fp16, transposed), V (fp16)
#pragma unroll
    for (int rep = 0; rep < 2; rep++) {
        int idx = rep * 256 + tid;      // 0..511
        int i  = idx >> 3;
        int j8 = (idx & 7) * 8;
        uint4 qu = *(const uint4*)(g_qh + rowbase + (size_t)i * DM + j8);
        uint4 ku = *(const uint4*)(g_kh + rowbase + (size_t)i * DM + j8);
        uint4 vu = *(const uint4*)(g_vh + rowbase + (size_t)i * DM + j8);
        const __half2* qh2 = (const __half2*)&qu;
        const __half2* kh2 = (const __half2*)&ku;
        const __half2* vh2 = (const __half2*)&vu;
#pragma unroll
        for (int t = 0; t < 4; t++) {
            float2 qf = __half22float2(qh2[t]);
            float2 kf = __half22float2(kh2[t]);
            float2 vf = __half22float2(vh2[t]);
            Qs[i * 68 + j8 + t * 2 + 0] = qf.x;
            Qs[i * 68 + j8 + t * 2 + 1] = qf.y;
            Kt[(j8 + t * 2 + 0) * 68 + i] = kf.x;
            Kt[(j8 + t * 2 + 1) * 68 + i] = kf.y;
            Vs[i * 68 + j8 + t * 2 + 0] = vf.x;
            Vs[i * 68 + j8 + t * 2 + 1] = vf.y;
        }
    }
    __syncthreads();

    const int ti = (tid >> 4) * 4;
    const int tj = (tid & 15) * 4;

    float accO[4][4];
    float at[4][4];
#pragma unroll
    for (int a = 0; a < 4; a++)
#pragma unroll
        for (int b = 0; b < 4; b++) { accO[a][b] = 0.f; at[a][b] = 0.f; }

    for (int d = 0; d < 64; d++) {
        float qa[4];
        qa[0] = Qs[(ti + 0) * 68 + d]; qa[1] = Qs[(ti + 1) * 68 + d];
        qa[2] = Qs[(ti + 2) * 68 + d]; qa[3] = Qs[(ti + 3) * 68 + d];
        float4 pp = *(const float4*)&Ps[d * 68 + tj];
        float4 kb = *(const float4*)&Kt[d * 68 + tj];
        float pb[4] = {pp.x, pp.y, pp.z, pp.w};
        float kv[4] = {kb.x, kb.y, kb.z, kb.w};
#pragma unroll
        for (int a = 0; a < 4; a++)
#pragma unroll
            for (int b = 0; b < 4; b++) {
                accO[a][b] = fmaf(qa[a], pb[b], accO[a][b]);
                at[a][b]   = fmaf(qa[a], kv[b], at[a][b]);
            }
    }
#pragma unroll
    for (int a = 0; a < 4; a++)
#pragma unroll
        for (int b = 0; b < 4; b++)
            if (tj + b > ti + a) at[a][b] = 0.f;

    __syncthreads();

    float* As = Ps;
    float* Zc = Kt;
#pragma unroll
    for (int a = 0; a < 4; a++) {
        float4 o; o.x = at[a][0]; o.y = at[a][1]; o.z = at[a][2]; o.w = at[a][3];
        *(float4*)&As[(ti + a) * 68 + tj] = o;
    }
    if (tid < 64) {
        float z = g_qs[((size_t)nh * NC + c) * HD + tid];
        for (int i = 0; i < 64; i++) {
            z += Qs[i * 68 + tid];
            Zc[i * 68 + tid] = z;
        }
    }
    __syncthreads();

    for (int j = 0; j < 64; j++) {
        float aa[4];
        aa[0] = As[(ti + 0) * 68 + j]; aa[1] = As[(ti + 1) * 68 + j];
        aa[2] = As[(ti + 2) * 68 + j]; aa[3] = As[(ti + 3) * 68 + j];
        float4 vv = *(const float4*)&Vs[j * 68 + tj];
        float vb[4] = {vv.x, vv.y, vv.z, vv.w};
#pragma unroll
        for (int a = 0; a < 4; a++)
#pragma unroll
            for (int b = 0; b < 4; b++)
                accO[a][b] = fmaf(aa[a], vb[b], accO[a][b]);
    }

#pragma unroll
    for (int a = 0; a < 4; a++) {
        float4 z4 = *(const float4*)&Zc[(ti + a) * 68 + tj];
        __half2 h01 = __floats2half2_rn(accO[a][0] / z4.x, accO[a][1] / z4.y);
        __half2 h23 = __floats2half2_rn(accO[a][2] / z4.z, accO[a][3] / z4.w);
        size_t eo = rowbase + (size_t)(ti + a) * DM + tj;
        *(__half2*)(g_Ah + eo)     = h01;
        *(__half2*)(g_Ah + eo + 2) = h23;
    }
}

// ---------------------------------------------------------------------------
extern "C" void kernel_launch(void* const* d_in, const int* in_sizes, int n_in,
                              void* d_out, int out_size)
{
    const float* queries = (const float*)d_in[0];
    const float* keys    = (const float*)d_in[1];
    const float* values  = (const float*)d_in[2];
    const float* Wq = (const float*)d_in[3];
    const float* bq = (const float*)d_in[4];
    const float* Wk = (const float*)d_in[5];
    const float* bk = (const float*)d_in[6];
    const float* Wv = (const float*)d_in[7];
    const float* bv = (const float*)d_in[8];
    const float* Wo = (const float*)d_in[9];
    const float* bo = (const float*)d_in[10];
    float* out = (float*)d_out;

    __half* qh; cudaGetSymbolAddress((void**)&qh,  g_qh);
    __half* kh; cudaGetSymbolAddress((void**)&kh,  g_kh);
    __half* vh; cudaGetSymbolAddress((void**)&vh,  g_vh);
    __half* ah; cudaGetSymbolAddress((void**)&ah,  g_Ah);
    __half* w;  cudaGetSymbolAddress((void**)&w,   g_W);

    static bool attrSet = false;
    if (!attrSet) {
        cudaFuncSetAttribute(gemm_f16, cudaFuncAttributeMaxDynamicSharedMemorySize,
                             GEMM_SMEM);
        cudaFuncSetAttribute(chunk_out_kernel,
                             cudaFuncAttributeMaxDynamicSharedMemorySize,
                             CO_SMEM);
        attrSet = true;
    }

    const int splitBlocks = (MROWS * DM / 4 + 255) / 256;

    // Split inputs and all 4 weights (batched, single-term fp16)
    split_input3<<<dim3(splitBlocks, 3), 256>>>(queries, keys, values,
                                                MROWS * DM / 4);
    transpose4<<<dim3(DM / 32, DM / 32, 4), 256>>>(Wq, Wk, Wv, Wo);

    // Fused Q/K/V projections: all outputs fp16 (q/k with elu+1)
    gemm_f16<<<dim3(DM / 128, MROWS / 128, 3), 256, GEMM_SMEM>>>(
        ah, w, bq, bk, bv, nullptr, qh, kh, vh, 0x3, 0x7);

    // Chunked causal linear attention
    dim3 chunkGrid(NC, NH);
    chunk_sums_kernel<<<chunkGrid, 256>>>();
    prefix_kernel<<<dim3(NH, 8), 256>>>();
    chunk_out_kernel<<<chunkGrid, 256, CO_SMEM>>>();

    // Output projection: att (slot 0 of g_Ah) @ Wo (slot 3) + bo -> fp32 out
    gemm_f16<<<dim3(DM / 128, MROWS / 128, 1), 256, GEMM_SMEM>>>(
        ah, w + 3 * (size_t)DM * DM, bo, bo, bo, out, qh, kh, vh, 0x0, 0x0);
}

// round 17
// speedup vs baseline: 1.0637x; 1.0199x over previous
#include <cuda_runtime.h>
#include <cuda_fp16.h>
#include <math.h>
#include <cstdint>

// Problem constants
#define NB 4
#define LSEQ 2048
#define DM 1024
#define NHEAD 16
#define HD 64
#define MROWS (NB * LSEQ)   // 8192
#define CH 64
#define NC (LSEQ / CH)      // 32
#define NH (NB * NHEAD)     // 64

// Scratch (device globals; no allocation allowed)
__device__ __half g_qh[MROWS * DM];         // elu(q)+1 fp16
__device__ __half g_kh[MROWS * DM];         // elu(k)+1 fp16
__device__ __half g_vh[MROWS * DM];         // v projection fp16
__device__ float g_S [NH * NC * HD * HD];
__device__ float g_qs[NH * NC * HD];

// fp16 GEMM operand scratch
__device__ __half g_Ah[3 * MROWS * DM];     // q,k,v inputs (att reuses slot 0)
__device__ __half g_W [4 * DM * DM];        // transposed [n][k]; slot 3 = Wo

// ---------------------------------------------------------------------------
// PTX helpers
// ---------------------------------------------------------------------------
__device__ __forceinline__ uint32_t smem_u32(const void* p) {
    uint32_t a;
    asm("{ .reg .u64 t; cvta.to.shared.u64 t, %1; cvt.u32.u64 %0, t; }"
        : "=r"(a) : "l"(p));
    return a;
}

#define CPASYNC16(s, g) \
    asm volatile("cp.async.cg.shared.global [%0], [%1], 16;" \
                 :: "r"(s), "l"(g) : "memory")
#define CPCOMMIT() asm volatile("cp.async.commit_group;" ::: "memory")
#define CPWAIT2()  asm volatile("cp.async.wait_group 2;" ::: "memory")

__device__ __forceinline__ void ldsm4(uint32_t* r, uint32_t a) {
    asm volatile("ldmatrix.sync.aligned.m8n8.x4.shared.b16 {%0,%1,%2,%3}, [%4];"
        : "=r"(r[0]), "=r"(r[1]), "=r"(r[2]), "=r"(r[3]) : "r"(a));
}
__device__ __forceinline__ void ldsm2(uint32_t* r, uint32_t a) {
    asm volatile("ldmatrix.sync.aligned.m8n8.x2.shared.b16 {%0,%1}, [%2];"
        : "=r"(r[0]), "=r"(r[1]) : "r"(a));
}
__device__ __forceinline__ void mma16816(float* c, const uint32_t* a, const uint32_t* b) {
    asm volatile("mma.sync.aligned.m16n8k16.row.col.f32.f16.f16.f32 "
        "{%0,%1,%2,%3}, {%4,%5,%6,%7}, {%8,%9}, {%0,%1,%2,%3};"
        : "+f"(c[0]), "+f"(c[1]), "+f"(c[2]), "+f"(c[3])
        : "r"(a[0]), "r"(a[1]), "r"(a[2]), "r"(a[3]), "r"(b[0]), "r"(b[1]));
}

// ---------------------------------------------------------------------------
// split_input3: fp32 -> fp16, batched over z = {q,k,v}
// ---------------------------------------------------------------------------
__global__ void __launch_bounds__(256) split_input3(
    const float* __restrict__ Xq, const float* __restrict__ Xk,
    const float* __restrict__ Xv, int n4)
{
    int z = blockIdx.y;
    const float* X = (z == 0) ? Xq : (z == 1) ? Xk : Xv;
    __half* out = g_Ah + (size_t)z * MROWS * DM;
    int idx = blockIdx.x * 256 + threadIdx.x;
    if (idx >= n4) return;
    float4 x = ((const float4*)X)[idx];
    __half2* op = (__half2*)out;
    op[idx * 2 + 0] = __floats2half2_rn(x.x, x.y);
    op[idx * 2 + 1] = __floats2half2_rn(x.z, x.w);
}

// transpose4: W[k][n] fp32 -> Wt fp16 [n][k], batched over 4 weights
__global__ void __launch_bounds__(256) transpose4(
    const float* __restrict__ W0, const float* __restrict__ W1,
    const float* __restrict__ W2, const float* __restrict__ W3)
{
    __shared__ float t[32][33];
    int z = blockIdx.z;
    const float* W = (z == 0) ? W0 : (z == 1) ? W1 : (z == 2) ? W2 : W3;
    __half* hi = g_W + (size_t)z * DM * DM;
    int bx = blockIdx.x * 32;   // n base
    int by = blockIdx.y * 32;   // k base
    int tx = threadIdx.x & 31;
    int ty = threadIdx.x >> 5;  // 0..7
#pragma unroll
    for (int i = 0; i < 4; i++) {
        int k = by + ty + i * 8;
        t[ty + i * 8][tx] = W[(size_t)k * DM + bx + tx];
    }
    __syncthreads();
#pragma unroll
    for (int i = 0; i < 4; i++) {
        int n = bx + ty + i * 8;
        int k = by + tx;
        hi[(size_t)n * DM + k] = __float2half_rn(t[tx][ty + i * 8]);
    }
}

// ---------------------------------------------------------------------------
// fp16 single-term GEMM: C = A @ W + bias (+elu+1)
// BM=BN=128, BK=32, 256 threads, warp tile 64x32, cp.async 3-stage, 2 CTA/SM.
// ---------------------------------------------------------------------------
#define ARR 10240            // 128 rows * 80B
#define STG (2 * ARR)        // 20480 per stage
#define NSTAGE 3
#define GEMM_SMEM (NSTAGE * STG)  // 61440

__device__ __forceinline__ void load_stage(
    uint32_t sbase, int tid, int k0,
    const __half* pA, const __half* pW)
{
#pragma unroll
    for (int rep = 0; rep < 2; rep++) {
        int l = rep * 256 + tid;        // 0..511
        int row = l >> 2;               // 0..127
        int ch = l & 3;                 // 0..3 (16B chunks)
        uint32_t so = sbase + (uint32_t)row * 80 + ch * 16;
        size_t go = (size_t)row * DM + k0 + ch * 8;
        CPASYNC16(so + 0 * ARR, pA + go);
        CPASYNC16(so + 1 * ARR, pW + go);
    }
}

__global__ void __launch_bounds__(256, 2) gemm_f16(
    const __half* __restrict__ Ah, const __half* __restrict__ W,
    const float* __restrict__ b0, const float* __restrict__ b1,
    const float* __restrict__ b2,
    float* __restrict__ C0,
    __half* __restrict__ H0, __half* __restrict__ H1, __half* __restrict__ H2,
    int actMask, int halfMask)
{
    extern __shared__ char smem[];
    const uint32_t sb = smem_u32(smem);
    const int z = blockIdx.z;
    const int tid = threadIdx.x;
    const int wid = tid >> 5;
    const int lid = tid & 31;
    const int rowBase = blockIdx.y * 128;
    const int colBase = blockIdx.x * 128;
    const int warpM = (wid >> 2) * 64;
    const int warpN = (wid & 3) * 32;

    const float* bias = (z == 0) ? b0 : (z == 1) ? b1 : b2;
    const int act = (actMask >> z) & 1;
    const int hout = (halfMask >> z) & 1;

    const __half* pA = Ah + (size_t)z * MROWS * DM + (size_t)rowBase * DM;
    const __half* pW = W  + (size_t)z * DM * DM + (size_t)colBase * DM;

    float acc[4][4][4];
#pragma unroll
    for (int i = 0; i < 4; i++)
#pragma unroll
        for (int j = 0; j < 4; j++)
#pragma unroll
            for (int e = 0; e < 4; e++) acc[i][j][e] = 0.f;

    // prologue: stages 0, 1
    load_stage(sb + 0 * STG, tid, 0, pA, pW);
    CPCOMMIT();
    load_stage(sb + 1 * STG, tid, 32, pA, pW);
    CPCOMMIT();

    const int aRow = warpM + (lid & 15);
    const uint32_t aCol = ((lid >> 4) & 1) * 16;
    const int bRow = warpN + (lid & 7);
    const uint32_t bCol = ((lid >> 3) & 1) * 16;

    for (int c = 0; c < 32; c++) {
        if (c + 2 < 32)
            load_stage(sb + ((c + 2) % NSTAGE) * STG, tid, (c + 2) * 32, pA, pW);
        CPCOMMIT();          // possibly-empty group keeps the count uniform
        CPWAIT2();           // <=2 pending -> stage c complete
        __syncthreads();

        const uint32_t stage = sb + (c % NSTAGE) * STG;
#pragma unroll
        for (int kk = 0; kk < 2; kk++) {
            const uint32_t aOff = (uint32_t)kk * 32 + aCol;
            const uint32_t bOff = (uint32_t)kk * 32 + bCol;
            uint32_t fB[4][2];
#pragma unroll
            for (int ni = 0; ni < 4; ni++)
                ldsm2(fB[ni], stage + (uint32_t)(bRow + ni * 8) * 80 + bOff + 1 * ARR);
#pragma unroll
            for (int mi = 0; mi < 4; mi++) {
                uint32_t fA[4];
                ldsm4(fA, stage + (uint32_t)(aRow + mi * 16) * 80 + aOff);
#pragma unroll
                for (int ni = 0; ni < 4; ni++)
                    mma16816(acc[mi][ni], fA, fB[ni]);
            }
        }
        __syncthreads();
    }

    // epilogue
    __half* H = (z == 0) ? H0 : (z == 1) ? H1 : H2;
#pragma unroll
    for (int mi = 0; mi < 4; mi++) {
        int r0 = rowBase + warpM + mi * 16 + (lid >> 2);
#pragma unroll
        for (int ni = 0; ni < 4; ni++) {
            int col = colBase + warpN + ni * 8 + (lid & 3) * 2;
            float2 b2v = *(const float2*)(bias + col);
            float v0 = acc[mi][ni][0] + b2v.x;
            float v1 = acc[mi][ni][1] + b2v.y;
            float v2 = acc[mi][ni][2] + b2v.x;
            float v3 = acc[mi][ni][3] + b2v.y;
            if (act) {
                v0 = (v0 > 0.f) ? (v0 + 1.f) : expf(v0);
                v1 = (v1 > 0.f) ? (v1 + 1.f) : expf(v1);
                v2 = (v2 > 0.f) ? (v2 + 1.f) : expf(v2);
                v3 = (v3 > 0.f) ? (v3 + 1.f) : expf(v3);
            }
            if (hout) {
                *(__half2*)(H + (size_t)r0 * DM + col)       = __floats2half2_rn(v0, v1);
                *(__half2*)(H + (size_t)(r0 + 8) * DM + col) = __floats2half2_rn(v2, v3);
            } else {
                float2 o0; o0.x = v0; o0.y = v1;
                float2 o1; o1.x = v2; o1.y = v3;
                *(float2*)(C0 + (size_t)r0 * DM + col) = o0;
                *(float2*)(C0 + (size_t)(r0 + 8) * DM + col) = o1;
            }
        }
    }
}

// ---------------------------------------------------------------------------
// Attention kernels (FFMA; q read as fp16, converted once at smem fill)
// ---------------------------------------------------------------------------
__global__ void __launch_bounds__(256) chunk_sums_kernel()
{
    const int c = blockIdx.x;
    const int nh = blockIdx.y;
    const int n = nh >> 4;
    const int h = nh & 15;
    const int tid = threadIdx.x;

    __shared__ float Ks[64][68];
    __shared__ float Vs[64][68];
    __shared__ float qsum[4][72];

    const size_t rowbase = ((size_t)(n * LSEQ + c * CH)) * DM + h * HD;

    // qp partial column sums from fp16 q
    {
        int col = tid & 63;
        int qtr = tid >> 6;     // 0..3
        float s = 0.f;
        const __half* qb = g_qh + rowbase + (size_t)(qtr * 16) * DM + col;
#pragma unroll
        for (int i = 0; i < 16; i++)
            s += __half2float(qb[(size_t)i * DM]);
        qsum[qtr][col] = s;
    }

#pragma unroll
    for (int rep = 0; rep < 2; rep++) {
        int idx = rep * 256 + tid;      // 0..511
        int i  = idx >> 3;              // row
        int j8 = (idx & 7) * 8;         // col base
        uint4 ku = *(const uint4*)(g_kh + rowbase + (size_t)i * DM + j8);
        uint4 vu = *(const uint4*)(g_vh + rowbase + (size_t)i * DM + j8);
        const __half2* kh2 = (const __half2*)&ku;
        const __half2* vh2 = (const __half2*)&vu;
#pragma unroll
        for (int t = 0; t < 4; t++) {
            float2 kf = __half22float2(kh2[t]);
            float2 vf = __half22float2(vh2[t]);
            Ks[i][j8 + t * 2 + 0] = kf.x;
            Ks[i][j8 + t * 2 + 1] = kf.y;
            Vs[i][j8 + t * 2 + 0] = vf.x;
            Vs[i][j8 + t * 2 + 1] = vf.y;
        }
    }
    __syncthreads();

    const int td = (tid >> 4) * 4;
    const int tk = (tid & 15) * 4;
    float acc[4][4];
#pragma unroll
    for (int a = 0; a < 4; a++)
#pragma unroll
        for (int b = 0; b < 4; b++) acc[a][b] = 0.f;

    for (int i = 0; i < 64; i++) {
        float ka[4];
        ka[0] = Ks[i][td + 0]; ka[1] = Ks[i][td + 1];
        ka[2] = Ks[i][td + 2]; ka[3] = Ks[i][td + 3];
        float4 vv = *(const float4*)&Vs[i][tk];
        float vb[4] = {vv.x, vv.y, vv.z, vv.w};
#pragma unroll
        for (int a = 0; a < 4; a++)
#pragma unroll
            for (int b = 0; b < 4; b++)
                acc[a][b] = fmaf(ka[a], vb[b], acc[a][b]);
    }

    float* Sp = g_S + ((size_t)nh * NC + c) * (HD * HD);
#pragma unroll
    for (int a = 0; a < 4; a++) {
        float4 o; o.x=acc[a][0]; o.y=acc[a][1]; o.z=acc[a][2]; o.w=acc[a][3];
        *(float4*)&Sp[(td + a) * HD + tk] = o;
    }

    if (tid < 64) {
        float s = qsum[0][tid] + qsum[1][tid] + qsum[2][tid] + qsum[3][tid];
        g_qs[((size_t)nh * NC + c) * HD + tid] = s;
    }
}

// Parallel prefix: grid (NH, 8), 256 threads; each thread scans 2 elements.
__global__ void __launch_bounds__(256) prefix_kernel()
{
    const int nh = blockIdx.x;
    const int seg = blockIdx.y;     // 0..7
    const int tid = threadIdx.x;
    const int e0 = seg * 512 + tid;

    float r0 = 0.f, r1 = 0.f;
    for (int c = 0; c < NC; c++) {
        float* Sp = g_S + ((size_t)nh * NC + c) * (HD * HD);
        float t0 = Sp[e0];       Sp[e0] = r0;       r0 += t0;
        float t1 = Sp[e0 + 256]; Sp[e0 + 256] = r1; r1 += t1;
    }

    if (seg == 0 && tid < 64) {
        float r = 0.f;
        for (int c = 0; c < NC; c++) {
            float* qp = g_qs + ((size_t)nh * NC + c) * HD + tid;
            float t = *qp;
            *qp = r;
            r += t;
        }
    }
}

// chunk_out: O = (tril(Qp Kp^T) V + Qp P) / Z, fp16 out into g_Ah[0].
// Causal-bounded AV loop + 4-way parallel Z scan.
#define TS (64 * 68)
#define CO_SMEM (4 * TS * 4)   // 69632 bytes
__global__ void __launch_bounds__(256, 2) chunk_out_kernel()
{
    extern __shared__ float fsm[];
    float* Qs = fsm;            // [i][d]
    float* Kt = fsm + TS;       // [d][i]  -> Zc later
    float* Vs = fsm + 2 * TS;   // [j][k]
    float* Ps = fsm + 3 * TS;   // [d][k]  -> As later
    __shared__ float qtot[4][68];

    const int c = blockIdx.x;
    const int nh = blockIdx.y;
    const int n = nh >> 4;
    const int h = nh & 15;
    const int tid = threadIdx.x;

    const size_t rowbase = ((size_t)(n * LSEQ + c * CH)) * DM + h * HD;
    const float* Sp = g_S + ((size_t)nh * NC + c) * (HD * HD);

    // P (fp32)
#pragma unroll
    for (int rep = 0; rep < 4; rep++) {
        int idx = rep * 256 + tid;
        float4 p = *(const float4*)(Sp + idx * 4);
        int d = (idx * 4) >> 6;
        int kk = (idx * 4) & 63;
        *(float4*)&Ps[d * 68 + kk] = p;
    }
    // Q (fp16 -> fp32 smem), K (fp16, transposed), V (fp16)
#pragma unroll
    for (int rep = 0; rep < 2; rep++) {
        int idx = rep * 256 + tid;      // 0..511
        int i  = idx >> 3;
        int j8 = (idx & 7) * 8;
        uint4 qu = *(const uint4*)(g_qh + rowbase + (size_t)i * DM + j8);
        uint4 ku = *(const uint4*)(g_kh + rowbase + (size_t)i * DM + j8);
        uint4 vu = *(const uint4*)(g_vh + rowbase + (size_t)i * DM + j8);
        const __half2* qh2 = (const __half2*)&qu;
        const __half2* kh2 = (const __half2*)&ku;
        const __half2* vh2 = (const __half2*)&vu;
#pragma unroll
        for (int t = 0; t < 4; t++) {
            float2 qf = __half22float2(qh2[t]);
            float2 kf = __half22float2(kh2[t]);
            float2 vf = __half22float2(vh2[t]);
            Qs[i * 68 + j8 + t * 2 + 0] = qf.x;
            Qs[i * 68 + j8 + t * 2 + 1] = qf.y;
            Kt[(j8 + t * 2 + 0) * 68 + i] = kf.x;
            Kt[(j8 + t * 2 + 1) * 68 + i] = kf.y;
            Vs[i * 68 + j8 + t * 2 + 0] = vf.x;
            Vs[i * 68 + j8 + t * 2 + 1] = vf.y;
        }
    }
    __syncthreads();

    const int ti = (tid >> 4) * 4;
    const int tj = (tid & 15) * 4;

    float accO[4][4];
    float at[4][4];
#pragma unroll
    for (int a = 0; a < 4; a++)
#pragma unroll
        for (int b = 0; b < 4; b++) { accO[a][b] = 0.f; at[a][b] = 0.f; }

    // fused loop: one Qs read feeds Q·P and Q·Kt^T
    for (int d = 0; d < 64; d++) {
        float qa[4];
        qa[0] = Qs[(ti + 0) * 68 + d]; qa[1] = Qs[(ti + 1) * 68 + d];
        qa[2] = Qs[(ti + 2) * 68 + d]; qa[3] = Qs[(ti + 3) * 68 + d];
        float4 pp = *(const float4*)&Ps[d * 68 + tj];
        float4 kb = *(const float4*)&Kt[d * 68 + tj];
        float pb[4] = {pp.x, pp.y, pp.z, pp.w};
        float kv[4] = {kb.x, kb.y, kb.z, kb.w};
#pragma unroll
        for (int a = 0; a < 4; a++)
#pragma unroll
            for (int b = 0; b < 4; b++) {
                accO[a][b] = fmaf(qa[a], pb[b], accO[a][b]);
                at[a][b]   = fmaf(qa[a], kv[b], at[a][b]);
            }
    }
#pragma unroll
    for (int a = 0; a < 4; a++)
#pragma unroll
        for (int b = 0; b < 4; b++)
            if (tj + b > ti + a) at[a][b] = 0.f;

    __syncthreads();   // all reads of Ps/Kt complete

    float* As = Ps;
    float* Zc = Kt;
#pragma unroll
    for (int a = 0; a < 4; a++) {
        float4 o; o.x = at[a][0]; o.y = at[a][1]; o.z = at[a][2]; o.w = at[a][3];
        *(float4*)&As[(ti + a) * 68 + tj] = o;
    }

    // Z scan pass 1: (col, quarter) local 16-row cumsum in registers
    const int zcol = tid & 63;
    const int zq   = tid >> 6;    // 0..3
    float zloc[16];
    {
        float s = 0.f;
#pragma unroll
        for (int r = 0; r < 16; r++) {
            s += Qs[(zq * 16 + r) * 68 + zcol];
            zloc[r] = s;
        }
        qtot[zq][zcol] = s;
    }
    __syncthreads();   // As + qtot visible

    // Z scan pass 2: add quarter-prefix offset, write Zc (disjoint from As/Vs)
    {
        float off = g_qs[((size_t)nh * NC + c) * HD + zcol];
#pragma unroll
        for (int p = 0; p < 3; p++)
            if (p < zq) off += qtot[p][zcol];
#pragma unroll
        for (int r = 0; r < 16; r++)
            Zc[(zq * 16 + r) * 68 + zcol] = off + zloc[r];
    }

    // accO += A·V with causal bound: warp w's rows are <= 8w+7 -> j < 8w+8
    const int jmax = ((tid >> 5) + 1) * 8;
    for (int j = 0; j < jmax; j++) {
        float aa[4];
        aa[0] = As[(ti + 0) * 68 + j]; aa[1] = As[(ti + 1) * 68 + j];
        aa[2] = As[(ti + 2) * 68 + j]; aa[3] = As[(ti + 3) * 68 + j];
        float4 vv = *(const float4*)&Vs[j * 68 + tj];
        float vb[4] = {vv.x, vv.y, vv.z, vv.w};
#pragma unroll
        for (int a = 0; a < 4; a++)
#pragma unroll
            for (int b = 0; b < 4; b++)
                accO[a][b] = fmaf(aa[a], vb[b], accO[a][b]);
    }

    __syncthreads();   // Zc writes visible to all readers

#pragma unroll
    for (int a = 0; a < 4; a++) {
        float4 z4 = *(const float4*)&Zc[(ti + a) * 68 + tj];
        __half2 h01 = __floats2half2_rn(accO[a][0] / z4.x, accO[a][1] / z4.y);
        __half2 h23 = __floats2half2_rn(accO[a][2] / z4.z, accO[a][3] / z4.w);
        size_t eo = rowbase + (size_t)(ti + a) * DM + tj;
        *(__half2*)(g_Ah + eo)     = h01;
        *(__half2*)(g_Ah + eo + 2) = h23;
    }
}

// ---------------------------------------------------------------------------
extern "C" void kernel_launch(void* const* d_in, const int* in_sizes, int n_in,
                              void* d_out, int out_size)
{
    const float* queries = (const float*)d_in[0];
    const float* keys    = (const float*)d_in[1];
    const float* values  = (const float*)d_in[2];
    const float* Wq = (const float*)d_in[3];
    const float* bq = (const float*)d_in[4];
    const float* Wk = (const float*)d_in[5];
    const float* bk = (const float*)d_in[6];
    const float* Wv = (const float*)d_in[7];
    const float* bv = (const float*)d_in[8];
    const float* Wo = (const float*)d_in[9];
    const float* bo = (const float*)d_in[10];
    float* out = (float*)d_out;

    __half* qh; cudaGetSymbolAddress((void**)&qh,  g_qh);
    __half* kh; cudaGetSymbolAddress((void**)&kh,  g_kh);
    __half* vh; cudaGetSymbolAddress((void**)&vh,  g_vh);
    __half* ah; cudaGetSymbolAddress((void**)&ah,  g_Ah);
    __half* w;  cudaGetSymbolAddress((void**)&w,   g_W);

    static bool attrSet = false;
    if (!attrSet) {
        cudaFuncSetAttribute(gemm_f16, cudaFuncAttributeMaxDynamicSharedMemorySize,
                             GEMM_SMEM);
        cudaFuncSetAttribute(chunk_out_kernel,
                             cudaFuncAttributeMaxDynamicSharedMemorySize,
                             CO_SMEM);
        attrSet = true;
    }

    const int splitBlocks = (MROWS * DM / 4 + 255) / 256;

    // Split inputs and all 4 weights (batched, single-term fp16)
    split_input3<<<dim3(splitBlocks, 3), 256>>>(queries, keys, values,
                                                MROWS * DM / 4);
    transpose4<<<dim3(DM / 32, DM / 32, 4), 256>>>(Wq, Wk, Wv, Wo);

    // Fused Q/K/V projections: all outputs fp16 (q/k with elu+1)
    gemm_f16<<<dim3(DM / 128, MROWS / 128, 3), 256, GEMM_SMEM>>>(
        ah, w, bq, bk, bv, nullptr, qh, kh, vh, 0x3, 0x7);

    // Chunked causal linear attention
    dim3 chunkGrid(NC, NH);
    chunk_sums_kernel<<<chunkGrid, 256>>>();
    prefix_kernel<<<dim3(NH, 8), 256>>>();
    chunk_out_kernel<<<chunkGrid, 256, CO_SMEM>>>();

    // Output projection: att (slot 0 of g_Ah) @ Wo (slot 3) + bo -> fp32 out
    gemm_f16<<<dim3(DM / 128, MROWS / 128, 1), 256, GEMM_SMEM>>>(
        ah, w + 3 * (size_t)DM * DM, bo, bo, bo, out, qh, kh, vh, 0x0, 0x0);
}